// round 1
// baseline (speedup 1.0000x reference)
#include <cuda_runtime.h>
#include <math.h>
#include <math_constants.h>

#define BATCH 128
#define T     250
#define DIN   700
#define H     256
#define DOUT  20
#define MTOT  (BATCH*T)
#define HW    (H/32)

// ---------------- scratch (static device globals; no dynamic alloc) ----------
__device__ float    g_XW1[MTOT*H];         // x@Wi1.T + bi1 + b11        (layer1 drive)
__device__ float    g_S12[MTOT*H];         // sp1@W12.T + b12 + b22      (layer2 drive)
__device__ float    g_O  [MTOT*DOUT];      // sp2@Wo.T + bo
__device__ unsigned g_sp1[MTOT*HW];        // layer1 spike bitmasks
__device__ unsigned g_sp2[MTOT*HW];        // layer2 spike bitmasks
__device__ float    g_W11t[H*H];           // transposed weights [i][j]
__device__ float    g_W12t[H*H];
__device__ float    g_W22t[H*H];
__device__ float    g_Wot [H*DOUT + 32];   // padded so lanes 20..31 never read OOB

// ---------------- transpose weights ------------------------------------------
__global__ void transpose_all(const float* __restrict__ W11, const float* __restrict__ W12,
                              const float* __restrict__ W22, const float* __restrict__ Wo)
{
    int idx = blockIdx.x * blockDim.x + threadIdx.x;
    if (idx < H*H) {
        int r = idx / H, c = idx % H;          // in[r][c] -> out[c][r]
        g_W11t[c*H + r] = W11[idx];
        g_W12t[c*H + r] = W12[idx];
        g_W22t[c*H + r] = W22[idx];
    }
    if (idx < DOUT*H) {
        int r = idx / H, c = idx % H;
        g_Wot[c*DOUT + r] = Wo[idx];
    }
}

// ---------------- Phase A: fp32 SGEMM (NT): C = A*B^T + bias1 + bias2 --------
// A = x [M x K] row-major, B = Wi1 [N x K] row-major, C = g_XW1 [M x N]
// Tiles: BM=64, BN=64, BK=16, 256 threads, 4x4 per thread.
__global__ __launch_bounds__(256)
void sgemm_nt(const float* __restrict__ A, const float* __restrict__ Bm,
              const float* __restrict__ bias1, const float* __restrict__ bias2,
              int M, int N, int K)
{
    __shared__ __align__(16) float As[16][68];
    __shared__ __align__(16) float Bs[16][68];
    float* C = g_XW1;

    int bm = blockIdx.x * 64, bn = blockIdx.y * 64;
    int tid  = threadIdx.x;
    int tx   = tid & 15;        // n-tile coord
    int ty   = tid >> 4;        // m-tile coord
    int lrow = tid >> 2;        // 0..63 load row
    int lk4  = (tid & 3) << 2;  // 0,4,8,12 k offset

    float acc[4][4] = {};

    for (int k0 = 0; k0 < K; k0 += 16) {
        int kk = k0 + lk4;
        float4 av = make_float4(0.f,0.f,0.f,0.f);
        float4 bv = make_float4(0.f,0.f,0.f,0.f);
        if (kk < K) {  // K%4==0 so a float4 is all-valid or all-invalid
            av = *(const float4*)(A  + (size_t)(bm + lrow)*K + kk);
            bv = *(const float4*)(Bm + (size_t)(bn + lrow)*K + kk);
        }
        __syncthreads();
        As[lk4+0][lrow]=av.x; As[lk4+1][lrow]=av.y; As[lk4+2][lrow]=av.z; As[lk4+3][lrow]=av.w;
        Bs[lk4+0][lrow]=bv.x; Bs[lk4+1][lrow]=bv.y; Bs[lk4+2][lrow]=bv.z; Bs[lk4+3][lrow]=bv.w;
        __syncthreads();
        #pragma unroll
        for (int k = 0; k < 16; ++k) {
            float4 a  = *(const float4*)&As[k][ty<<2];
            float4 bq = *(const float4*)&Bs[k][tx<<2];
            float am[4] = {a.x,a.y,a.z,a.w};
            float bn4[4] = {bq.x,bq.y,bq.z,bq.w};
            #pragma unroll
            for (int i = 0; i < 4; ++i)
                #pragma unroll
                for (int j = 0; j < 4; ++j)
                    acc[i][j] += am[i]*bn4[j];
        }
    }

    int ncol = bn + (tx<<2);
    float badd[4];
    #pragma unroll
    for (int j = 0; j < 4; ++j) badd[j] = bias1[ncol+j] + bias2[ncol+j];
    #pragma unroll
    for (int i = 0; i < 4; ++i) {
        int row = bm + (ty<<2) + i;
        #pragma unroll
        for (int j = 0; j < 4; ++j)
            C[(size_t)row*N + ncol + j] = acc[i][j] + badd[j];
    }
}

// ---------------- recurrent layer (adaptive LIF), one CTA per batch ----------
// layer==0: drive g_XW1, W g_W11t, out g_sp1 ; layer==1: drive g_S12, W g_W22t, out g_sp2
__global__ __launch_bounds__(H)
void recurrent_kernel(int layer, const float* __restrict__ mem0,
                      const float* __restrict__ tau_adp, const float* __restrict__ tau_m)
{
    const float*    drive   = (layer == 0) ? g_XW1  : g_S12;
    const float*    Wt      = (layer == 0) ? g_W11t : g_W22t;
    unsigned*       sp_bits = (layer == 0) ? g_sp1  : g_sp2;

    int b = blockIdx.x;
    int j = threadIdx.x;
    __shared__ unsigned mask[2][HW];

    float alpha = (float)exp(-1.0 / (double)tau_m[j]);
    float ro    = (float)exp(-1.0 / (double)tau_adp[j]);
    float mem   = mem0[b*H + j];
    float bb    = 0.01f;
    float sp    = 0.f;

    if (j < 2*HW) ((unsigned*)mask)[j] = 0u;
    __syncthreads();

    const float* dr = drive + (size_t)b*T*H + j;
    int cur = 0;
    float drv = dr[0];
    for (int t = 0; t < T; ++t) {
        float drv_next = (t+1 < T) ? dr[(size_t)(t+1)*H] : 0.f;
        float h = drv;
        #pragma unroll
        for (int w = 0; w < HW; ++w) {
            unsigned msk = mask[cur][w];   // same for whole warp -> uniform loop
            while (msk) {
                int i = __ffs(msk) - 1; msk &= msk - 1;
                h += Wt[(w*32 + i)*H + j]; // coalesced, L1-resident
            }
        }
        bb = ro*bb + (1.f - ro)*sp;
        float Bt = 0.01f + 1.8f*bb;
        mem = mem*alpha + (1.f - alpha)*h - Bt*sp;
        sp  = (mem - Bt > 0.f) ? 1.f : 0.f;

        unsigned bal = __ballot_sync(0xFFFFFFFFu, sp != 0.f);
        int nxt = cur ^ 1;
        if ((j & 31) == 0) {
            mask[nxt][j >> 5] = bal;
            sp_bits[((size_t)b*T + t)*HW + (j >> 5)] = bal;
        }
        __syncthreads();
        cur = nxt;
        drv = drv_next;
    }
}

// ---------------- bit-GEMM: out[m][j] = bias + sum_{i: bit(m,i)} Wt[i][j] ----
// which==0: g_sp1 x g_W12t -> g_S12 (N=256); which==1: g_sp2 x g_Wot -> g_O (N=20)
template<int N>
__global__ void bitgemm_kernel(int which, const float* __restrict__ bias1,
                               const float* __restrict__ bias2, int rows)
{
    const unsigned* bits = (which == 0) ? g_sp1  : g_sp2;
    const float*    Wt   = (which == 0) ? g_W12t : g_Wot;
    float*          out  = (which == 0) ? g_S12  : g_O;

    int j = threadIdx.x;
    bool act = j < N;
    float bs = 0.f;
    if (act) {
        if (bias1) bs += bias1[j];
        if (bias2) bs += bias2[j];
    }
    int m0 = blockIdx.x * rows;
    for (int r = 0; r < rows; ++r) {
        int m = m0 + r;
        float h = bs;
        #pragma unroll
        for (int w = 0; w < HW; ++w) {
            unsigned msk = bits[(size_t)m*HW + w];
            while (msk) {
                int i = __ffs(msk) - 1; msk &= msk - 1;
                h += Wt[(w*32 + i)*N + j];   // g_Wot padded: lanes j>=N read in-bounds junk
            }
        }
        if (act) out[(size_t)m*N + j] = h;
    }
}

// ---------------- output layer: memo recurrence + softmax accumulation -------
__global__ void output_kernel(const float* __restrict__ memo0,
                              const float* __restrict__ tau_m_o, float* __restrict__ outp)
{
    int b = blockIdx.x;
    int lane = threadIdx.x;       // 32
    bool act = lane < DOUT;
    int l = act ? lane : 0;

    float alpha = (float)exp(-1.0 / (double)tau_m_o[l]);
    float memo  = memo0[b*DOUT + l];
    float acc   = 0.f;
    const float* Ob = g_O + (size_t)b*T*DOUT;

    for (int t = 0; t < T; ++t) {
        float o = Ob[t*DOUT + l];
        memo = memo*alpha + (1.f - alpha)*o;
        float v = act ? memo : -CUDART_INF_F;
        #pragma unroll
        for (int off = 16; off; off >>= 1)
            v = fmaxf(v, __shfl_xor_sync(0xFFFFFFFFu, v, off));
        float e = act ? expf(memo - v) : 0.f;
        float s = e;
        #pragma unroll
        for (int off = 16; off; off >>= 1)
            s += __shfl_xor_sync(0xFFFFFFFFu, s, off);
        if (t > 10) acc += e / s;
    }
    if (act) outp[b*DOUT + lane] = acc;
}

// ---------------- launch ------------------------------------------------------
extern "C" void kernel_launch(void* const* d_in, const int* in_sizes, int n_in,
                              void* d_out, int out_size)
{
    const float* x        = (const float*)d_in[0];
    const float* mem1_0   = (const float*)d_in[1];
    const float* mem2_0   = (const float*)d_in[2];
    const float* memo_0   = (const float*)d_in[3];
    const float* Wi1      = (const float*)d_in[4];
    const float* bi1      = (const float*)d_in[5];
    const float* W11      = (const float*)d_in[6];
    const float* b11      = (const float*)d_in[7];
    const float* W12      = (const float*)d_in[8];
    const float* b12      = (const float*)d_in[9];
    const float* W22      = (const float*)d_in[10];
    const float* b22      = (const float*)d_in[11];
    const float* Wo       = (const float*)d_in[12];
    const float* bo       = (const float*)d_in[13];
    const float* tau_adp1 = (const float*)d_in[14];
    const float* tau_adp2 = (const float*)d_in[15];
    const float* tau_m1   = (const float*)d_in[16];
    const float* tau_m2   = (const float*)d_in[17];
    const float* tau_mo   = (const float*)d_in[18];
    float* outp = (float*)d_out;

    // 0) transpose weights
    transpose_all<<<(H*H + 255)/256, 256>>>(W11, W12, W22, Wo);

    // A) XW1 = x @ Wi1.T + bi1 + b11
    dim3 gA(MTOT/64, H/64);
    sgemm_nt<<<gA, 256>>>(x, Wi1, bi1, b11, MTOT, H, DIN);

    // B) layer-1 recurrence over all t (per-batch CTAs) -> sp1 bits
    recurrent_kernel<<<BATCH, H>>>(0, mem1_0, tau_adp1, tau_m1);

    // C) S12 = sp1 @ W12.T + b12 + b22   (parallel bit-GEMM over all (b,t))
    bitgemm_kernel<H><<<MTOT/20, H>>>(0, b12, b22, 20);

    // D) layer-2 recurrence -> sp2 bits
    recurrent_kernel<<<BATCH, H>>>(1, mem2_0, tau_adp2, tau_m2);

    // E1) O = sp2 @ Wo.T + bo   (parallel bit-GEMM, N=20)
    bitgemm_kernel<DOUT><<<MTOT/64, 32>>>(1, bo, nullptr, 64);

    // E2) memo recurrence + softmax accumulation
    output_kernel<<<BATCH, 32>>>(memo_0, tau_mo, outp);
}

// round 2
// speedup vs baseline: 1.7532x; 1.7532x over previous
#include <cuda_runtime.h>
#include <math.h>
#include <math_constants.h>

#define BATCH 128
#define T     250
#define DIN   700
#define H     256
#define DOUT  20
#define MTOT  (BATCH*T)
#define HW    (H/32)

// ---------------- scratch (static device globals; no dynamic alloc) ----------
__device__ float    g_XW1[MTOT*H];         // x@Wi1.T + bi1 + b11        (layer1 drive)
__device__ float    g_S12[MTOT*H];         // sp1@W12.T + b12 + b22      (layer2 drive)
__device__ float    g_O  [MTOT*DOUT];      // sp2@Wo.T + bo
__device__ unsigned g_sp1[MTOT*HW];        // layer1 spike bitmasks
__device__ unsigned g_sp2[MTOT*HW];        // layer2 spike bitmasks
__device__ float    g_W11t[H*H];           // transposed weights [i][j]
__device__ float    g_W12t[H*H];
__device__ float    g_W22t[H*H];
__device__ float    g_Wot [H*DOUT + 32];   // padded so lanes 20..31 never read OOB

// ---------------- transpose weights ------------------------------------------
__global__ void transpose_all(const float* __restrict__ W11, const float* __restrict__ W12,
                              const float* __restrict__ W22, const float* __restrict__ Wo)
{
    int idx = blockIdx.x * blockDim.x + threadIdx.x;
    if (idx < H*H) {
        int r = idx / H, c = idx % H;          // in[r][c] -> out[c][r]
        g_W11t[c*H + r] = W11[idx];
        g_W12t[c*H + r] = W12[idx];
        g_W22t[c*H + r] = W22[idx];
    }
    if (idx < DOUT*H) {
        int r = idx / H, c = idx % H;
        g_Wot[c*DOUT + r] = Wo[idx];
    }
}

// ---------------- Phase A: fp32 SGEMM (NT): C = A*B^T + bias1 + bias2 --------
// A = x [M x K], B = Wi1 [N x K] row-major, C = g_XW1 [M x N]
// 128x128 tile, BK=8, 256 threads, 8x8 per thread, double-buffered smem.
__global__ __launch_bounds__(256)
void sgemm128(const float* __restrict__ A, const float* __restrict__ Bm,
              const float* __restrict__ bias1, const float* __restrict__ bias2)
{
    const int N = H, K = DIN;
    __shared__ __align__(16) float As[2][8][132];
    __shared__ __align__(16) float Bs[2][8][132];
    float* C = g_XW1;

    int tid  = threadIdx.x;
    int bm   = blockIdx.x * 128, bn = blockIdx.y * 128;
    int lrow = tid >> 1;           // 0..127
    int lk4  = (tid & 1) << 2;     // 0 or 4
    int tx   = tid & 15;           // 0..15 -> n
    int ty   = tid >> 4;           // 0..15 -> m

    const float* Aptr = A  + (size_t)(bm + lrow) * K;
    const float* Bptr = Bm + (size_t)(bn + lrow) * K;

    float4 av, bv;
    {   // prefetch tile 0
        int k = lk4;
        bool v = (k < K);
        av = v ? *(const float4*)(Aptr + k) : make_float4(0.f,0.f,0.f,0.f);
        bv = v ? *(const float4*)(Bptr + k) : make_float4(0.f,0.f,0.f,0.f);
    }
    As[0][lk4+0][lrow]=av.x; As[0][lk4+1][lrow]=av.y; As[0][lk4+2][lrow]=av.z; As[0][lk4+3][lrow]=av.w;
    Bs[0][lk4+0][lrow]=bv.x; Bs[0][lk4+1][lrow]=bv.y; Bs[0][lk4+2][lrow]=bv.z; Bs[0][lk4+3][lrow]=bv.w;
    __syncthreads();

    float acc[8][8] = {};
    const int NIT = (K + 7) / 8;    // 88

    for (int it = 0; it < NIT; ++it) {
        int cur = it & 1, nxt = cur ^ 1;
        bool more = (it + 1 < NIT);
        if (more) {
            int k = (it + 1) * 8 + lk4;
            bool v = (k < K);       // K%4==0 -> float4 all-valid or all-invalid
            av = v ? *(const float4*)(Aptr + k) : make_float4(0.f,0.f,0.f,0.f);
            bv = v ? *(const float4*)(Bptr + k) : make_float4(0.f,0.f,0.f,0.f);
        }
        #pragma unroll
        for (int k = 0; k < 8; ++k) {
            float4 a0 = *(const float4*)&As[cur][k][ty*8];
            float4 a1 = *(const float4*)&As[cur][k][ty*8+4];
            float4 b0 = *(const float4*)&Bs[cur][k][tx*8];
            float4 b1 = *(const float4*)&Bs[cur][k][tx*8+4];
            float af[8] = {a0.x,a0.y,a0.z,a0.w,a1.x,a1.y,a1.z,a1.w};
            float bf[8] = {b0.x,b0.y,b0.z,b0.w,b1.x,b1.y,b1.z,b1.w};
            #pragma unroll
            for (int i = 0; i < 8; ++i)
                #pragma unroll
                for (int jj = 0; jj < 8; ++jj)
                    acc[i][jj] += af[i] * bf[jj];
        }
        if (more) {
            As[nxt][lk4+0][lrow]=av.x; As[nxt][lk4+1][lrow]=av.y; As[nxt][lk4+2][lrow]=av.z; As[nxt][lk4+3][lrow]=av.w;
            Bs[nxt][lk4+0][lrow]=bv.x; Bs[nxt][lk4+1][lrow]=bv.y; Bs[nxt][lk4+2][lrow]=bv.z; Bs[nxt][lk4+3][lrow]=bv.w;
            __syncthreads();
        }
    }

    int ncol = bn + tx*8;
    float badd[8];
    #pragma unroll
    for (int jj = 0; jj < 8; ++jj) badd[jj] = bias1[ncol+jj] + bias2[ncol+jj];
    #pragma unroll
    for (int i = 0; i < 8; ++i) {
        int row = bm + ty*8 + i;
        float4 o0 = make_float4(acc[i][0]+badd[0], acc[i][1]+badd[1], acc[i][2]+badd[2], acc[i][3]+badd[3]);
        float4 o1 = make_float4(acc[i][4]+badd[4], acc[i][5]+badd[5], acc[i][6]+badd[6], acc[i][7]+badd[7]);
        *(float4*)&C[(size_t)row*N + ncol    ] = o0;
        *(float4*)&C[(size_t)row*N + ncol + 4] = o1;
    }
}

// ---------------- recurrent layer (adaptive LIF), one CTA per batch ----------
__global__ __launch_bounds__(H)
void recurrent_kernel(int layer, const float* __restrict__ mem0,
                      const float* __restrict__ tau_adp, const float* __restrict__ tau_m)
{
    const float*    drive   = (layer == 0) ? g_XW1  : g_S12;
    const float*    Wt      = (layer == 0) ? g_W11t : g_W22t;
    unsigned*       sp_bits = (layer == 0) ? g_sp1  : g_sp2;

    int b = blockIdx.x;
    int j = threadIdx.x;
    __shared__ unsigned mask[2][HW];

    float alpha = (float)exp(-1.0 / (double)tau_m[j]);
    float ro    = (float)exp(-1.0 / (double)tau_adp[j]);
    float mem   = mem0[b*H + j];
    float bb    = 0.01f;
    float sp    = 0.f;

    if (j < 2*HW) ((unsigned*)mask)[j] = 0u;
    __syncthreads();

    const float* dr = drive + (size_t)b*T*H + j;
    int cur = 0;
    float drv = dr[0];
    for (int t = 0; t < T; ++t) {
        float drv_next = (t+1 < T) ? dr[(size_t)(t+1)*H] : 0.f;
        float h = drv;
        #pragma unroll
        for (int w = 0; w < HW; ++w) {
            unsigned msk = mask[cur][w];   // same for whole warp -> uniform loop
            while (msk) {
                int i = __ffs(msk) - 1; msk &= msk - 1;
                h += Wt[(w*32 + i)*H + j]; // coalesced, L1-resident
            }
        }
        bb = ro*bb + (1.f - ro)*sp;
        float Bt = 0.01f + 1.8f*bb;
        mem = mem*alpha + (1.f - alpha)*h - Bt*sp;
        sp  = (mem - Bt > 0.f) ? 1.f : 0.f;

        unsigned bal = __ballot_sync(0xFFFFFFFFu, sp != 0.f);
        int nxt = cur ^ 1;
        if ((j & 31) == 0) {
            mask[nxt][j >> 5] = bal;
            sp_bits[((size_t)b*T + t)*HW + (j >> 5)] = bal;
        }
        __syncthreads();
        cur = nxt;
        drv = drv_next;
    }
}

// ---------------- bit-GEMM: out[m][j] = bias + sum_{i: bit(m,i)} Wt[i][j] ----
// Row pairs (consecutive t) share a union-mask loop: shared loads + 2 ILP chains.
template<int N>
__global__ void bitgemm_kernel(int which, const float* __restrict__ bias1,
                               const float* __restrict__ bias2, int rows)
{
    const unsigned* bits = (which == 0) ? g_sp1  : g_sp2;
    const float*    Wt   = (which == 0) ? g_W12t : g_Wot;
    float*          out  = (which == 0) ? g_S12  : g_O;

    int j = threadIdx.x;
    bool act = j < N;
    float bs = 0.f;
    if (act) {
        if (bias1) bs += bias1[j];
        if (bias2) bs += bias2[j];
    }
    int m0 = blockIdx.x * rows;
    for (int r = 0; r < rows; r += 2) {
        int ma = m0 + r;
        const uint4* pa = (const uint4*)(bits + (size_t)ma*HW);
        uint4 qa0 = pa[0], qa1 = pa[1], qb0 = pa[2], qb1 = pa[3];
        unsigned wa[HW] = {qa0.x,qa0.y,qa0.z,qa0.w,qa1.x,qa1.y,qa1.z,qa1.w};
        unsigned wb[HW] = {qb0.x,qb0.y,qb0.z,qb0.w,qb1.x,qb1.y,qb1.z,qb1.w};
        float ha = bs, hb = bs;
        #pragma unroll
        for (int w = 0; w < HW; ++w) {
            unsigned a = wa[w], bm_ = wb[w];
            unsigned u = a | bm_;
            const float* base = Wt + w*32*N + j;
            while (u) {
                int i = __ffs(u) - 1; unsigned bit = 1u << i; u &= u - 1;
                float v = base[(size_t)i*N];
                if (a   & bit) ha += v;
                if (bm_ & bit) hb += v;
            }
        }
        if (act) {
            out[(size_t)ma*N + j]     = ha;
            out[(size_t)(ma+1)*N + j] = hb;
        }
    }
}

// ---------------- output layer: memo recurrence + softmax accumulation -------
__global__ void output_kernel(const float* __restrict__ memo0,
                              const float* __restrict__ tau_m_o, float* __restrict__ outp)
{
    int b = blockIdx.x;
    int lane = threadIdx.x;       // 32
    bool act = lane < DOUT;
    int l = act ? lane : 0;

    float alpha = (float)exp(-1.0 / (double)tau_m_o[l]);
    float memo  = memo0[b*DOUT + l];
    float acc   = 0.f;
    const float* Ob = g_O + (size_t)b*T*DOUT;

    for (int t = 0; t < T; ++t) {
        float o = Ob[t*DOUT + l];
        memo = memo*alpha + (1.f - alpha)*o;
        float v = act ? memo : -CUDART_INF_F;
        #pragma unroll
        for (int off = 16; off; off >>= 1)
            v = fmaxf(v, __shfl_xor_sync(0xFFFFFFFFu, v, off));
        float e = act ? expf(memo - v) : 0.f;
        float s = e;
        #pragma unroll
        for (int off = 16; off; off >>= 1)
            s += __shfl_xor_sync(0xFFFFFFFFu, s, off);
        if (t > 10) acc += e / s;
    }
    if (act) outp[b*DOUT + lane] = acc;
}

// ---------------- launch ------------------------------------------------------
extern "C" void kernel_launch(void* const* d_in, const int* in_sizes, int n_in,
                              void* d_out, int out_size)
{
    const float* x        = (const float*)d_in[0];
    const float* mem1_0   = (const float*)d_in[1];
    const float* mem2_0   = (const float*)d_in[2];
    const float* memo_0   = (const float*)d_in[3];
    const float* Wi1      = (const float*)d_in[4];
    const float* bi1      = (const float*)d_in[5];
    const float* W11      = (const float*)d_in[6];
    const float* b11      = (const float*)d_in[7];
    const float* W12      = (const float*)d_in[8];
    const float* b12      = (const float*)d_in[9];
    const float* W22      = (const float*)d_in[10];
    const float* b22      = (const float*)d_in[11];
    const float* Wo       = (const float*)d_in[12];
    const float* bo       = (const float*)d_in[13];
    const float* tau_adp1 = (const float*)d_in[14];
    const float* tau_adp2 = (const float*)d_in[15];
    const float* tau_m1   = (const float*)d_in[16];
    const float* tau_m2   = (const float*)d_in[17];
    const float* tau_mo   = (const float*)d_in[18];
    float* outp = (float*)d_out;

    // 0) transpose weights
    transpose_all<<<(H*H + 255)/256, 256>>>(W11, W12, W22, Wo);

    // A) XW1 = x @ Wi1.T + bi1 + b11   (128x128 tiled, double buffered)
    dim3 gA(MTOT/128, H/128);
    sgemm128<<<gA, 256>>>(x, Wi1, bi1, b11);

    // B) layer-1 recurrence over all t (per-batch CTAs) -> sp1 bits
    recurrent_kernel<<<BATCH, H>>>(0, mem1_0, tau_adp1, tau_m1);

    // C) S12 = sp1 @ W12.T + b12 + b22   (parallel pairwise bit-GEMM)
    bitgemm_kernel<H><<<MTOT/10, H>>>(0, b12, b22, 10);

    // D) layer-2 recurrence -> sp2 bits
    recurrent_kernel<<<BATCH, H>>>(1, mem2_0, tau_adp2, tau_m2);

    // E1) O = sp2 @ Wo.T + bo   (parallel pairwise bit-GEMM, N=20)
    bitgemm_kernel<DOUT><<<MTOT/16, 32>>>(1, bo, nullptr, 16);

    // E2) memo recurrence + softmax accumulation
    output_kernel<<<BATCH, 32>>>(memo_0, tau_mo, outp);
}

// round 3
// speedup vs baseline: 1.8934x; 1.0800x over previous
#include <cuda_runtime.h>
#include <math.h>
#include <math_constants.h>

#define BATCH 128
#define T     250
#define DIN   700
#define H     256
#define DOUT  20
#define MTOT  (BATCH*T)
#define HW    (H/32)

// ---------------- scratch (static device globals; no dynamic alloc) ----------
__device__ float    g_XW1[MTOT*H];         // x@Wi1.T + bi1 + b11   (layer1 drive)
__device__ float    g_S12[MTOT*H];         // sp1@W12.T + b12 + b22 (layer2 drive)
__device__ unsigned g_sp1[MTOT*HW];        // layer1 spike bitmasks
__device__ float    g_W11t[H*H];           // transposed weights [i][j]
__device__ float    g_W12t[H*H];
__device__ float    g_W22t[H*H];
__device__ float    g_Wot [H*DOUT];

// ---------------- transpose weights ------------------------------------------
__global__ void transpose_all(const float* __restrict__ W11, const float* __restrict__ W12,
                              const float* __restrict__ W22, const float* __restrict__ Wo)
{
    int idx = blockIdx.x * blockDim.x + threadIdx.x;
    if (idx < H*H) {
        int r = idx / H, c = idx % H;          // in[r][c] -> out[c][r]
        g_W11t[c*H + r] = W11[idx];
        g_W12t[c*H + r] = W12[idx];
        g_W22t[c*H + r] = W22[idx];
    }
    if (idx < DOUT*H) {
        int r = idx / H, c = idx % H;
        g_Wot[c*DOUT + r] = Wo[idx];
    }
}

// ---------------- Phase A: fp32 SGEMM (NT): C = A*B^T + bias1 + bias2 --------
// A = x [M x K], B = Wi1 [N x K] row-major, C = g_XW1 [M x N]
// 128x128 tile, BK=8, 256 threads, warp-tiled 64x32 per warp, 8x8 per thread.
// Lane mapping row=lane>>2, col=lane&3 -> conflict-free smem fragment reads.
__global__ __launch_bounds__(256)
void sgemm128(const float* __restrict__ A, const float* __restrict__ Bm,
              const float* __restrict__ bias1, const float* __restrict__ bias2)
{
    const int N = H, K = DIN;
    __shared__ __align__(16) float As[2][8][132];
    __shared__ __align__(16) float Bs[2][8][132];
    float* C = g_XW1;

    int tid  = threadIdx.x;
    int bm   = blockIdx.x * 128, bn = blockIdx.y * 128;
    int lrow = tid >> 1;           // 0..127 load row
    int lk4  = (tid & 1) << 2;     // 0 or 4
    int warp = tid >> 5;           // 0..7
    int lane = tid & 31;
    int wm   = (warp >> 2) * 64;   // warp m offset (0 or 64)
    int wn   = (warp & 3) * 32;    // warp n offset (0,32,64,96)
    int row  = lane >> 2;          // 0..7
    int col  = lane & 3;           // 0..3
    int moff = wm + row * 8;       // thread m offset within tile
    int noff = wn + col * 8;       // thread n offset within tile

    const float* Aptr = A  + (size_t)(bm + lrow) * K;
    const float* Bptr = Bm + (size_t)(bn + lrow) * K;

    float4 av, bv;
    {   // prefetch tile 0
        int k = lk4;
        bool v = (k < K);
        av = v ? *(const float4*)(Aptr + k) : make_float4(0.f,0.f,0.f,0.f);
        bv = v ? *(const float4*)(Bptr + k) : make_float4(0.f,0.f,0.f,0.f);
    }
    As[0][lk4+0][lrow]=av.x; As[0][lk4+1][lrow]=av.y; As[0][lk4+2][lrow]=av.z; As[0][lk4+3][lrow]=av.w;
    Bs[0][lk4+0][lrow]=bv.x; Bs[0][lk4+1][lrow]=bv.y; Bs[0][lk4+2][lrow]=bv.z; Bs[0][lk4+3][lrow]=bv.w;
    __syncthreads();

    float acc[8][8] = {};
    const int NIT = (K + 7) / 8;    // 88

    for (int it = 0; it < NIT; ++it) {
        int cur = it & 1, nxt = cur ^ 1;
        bool more = (it + 1 < NIT);
        if (more) {
            int k = (it + 1) * 8 + lk4;
            bool v = (k < K);       // K%4==0 -> float4 all-valid or all-invalid
            av = v ? *(const float4*)(Aptr + k) : make_float4(0.f,0.f,0.f,0.f);
            bv = v ? *(const float4*)(Bptr + k) : make_float4(0.f,0.f,0.f,0.f);
        }
        #pragma unroll
        for (int k = 0; k < 8; ++k) {
            float4 a0 = *(const float4*)&As[cur][k][moff];
            float4 a1 = *(const float4*)&As[cur][k][moff+4];
            float4 b0 = *(const float4*)&Bs[cur][k][noff];
            float4 b1 = *(const float4*)&Bs[cur][k][noff+4];
            float af[8] = {a0.x,a0.y,a0.z,a0.w,a1.x,a1.y,a1.z,a1.w};
            float bf[8] = {b0.x,b0.y,b0.z,b0.w,b1.x,b1.y,b1.z,b1.w};
            #pragma unroll
            for (int i = 0; i < 8; ++i)
                #pragma unroll
                for (int jj = 0; jj < 8; ++jj)
                    acc[i][jj] += af[i] * bf[jj];
        }
        if (more) {
            As[nxt][lk4+0][lrow]=av.x; As[nxt][lk4+1][lrow]=av.y; As[nxt][lk4+2][lrow]=av.z; As[nxt][lk4+3][lrow]=av.w;
            Bs[nxt][lk4+0][lrow]=bv.x; Bs[nxt][lk4+1][lrow]=bv.y; Bs[nxt][lk4+2][lrow]=bv.z; Bs[nxt][lk4+3][lrow]=bv.w;
            __syncthreads();
        }
    }

    int ncol = bn + noff;
    float badd[8];
    #pragma unroll
    for (int jj = 0; jj < 8; ++jj) badd[jj] = bias1[ncol+jj] + bias2[ncol+jj];
    #pragma unroll
    for (int i = 0; i < 8; ++i) {
        int rowg = bm + moff + i;
        float4 o0 = make_float4(acc[i][0]+badd[0], acc[i][1]+badd[1], acc[i][2]+badd[2], acc[i][3]+badd[3]);
        float4 o1 = make_float4(acc[i][4]+badd[4], acc[i][5]+badd[5], acc[i][6]+badd[6], acc[i][7]+badd[7]);
        *(float4*)&C[(size_t)rowg*N + ncol    ] = o0;
        *(float4*)&C[(size_t)rowg*N + ncol + 4] = o1;
    }
}

// ---------------- layer-1 recurrence (adaptive LIF), one CTA per batch -------
// 4-chain bit loop: 4 independent predicated loads per iteration -> MLP=4.
__global__ __launch_bounds__(H)
void recurrent1_kernel(const float* __restrict__ mem0,
                       const float* __restrict__ tau_adp, const float* __restrict__ tau_m)
{
    int b = blockIdx.x;
    int j = threadIdx.x;
    __shared__ __align__(16) unsigned mask[2][HW];

    float alpha = (float)exp(-1.0 / (double)tau_m[j]);
    float ro    = (float)exp(-1.0 / (double)tau_adp[j]);
    float mem   = mem0[b*H + j];
    float bb    = 0.01f;
    float sp    = 0.f;

    if (j < 2*HW) ((unsigned*)mask)[j] = 0u;
    __syncthreads();

    const float* dr = g_XW1 + (size_t)b*T*H + j;
    int cur = 0;
    float drv = dr[0];
    for (int t = 0; t < T; ++t) {
        float drv_next = (t+1 < T) ? dr[(size_t)(t+1)*H] : 0.f;
        uint4 mq0 = *(const uint4*)&mask[cur][0];
        uint4 mq1 = *(const uint4*)&mask[cur][4];
        unsigned msk[HW] = {mq0.x,mq0.y,mq0.z,mq0.w,mq1.x,mq1.y,mq1.z,mq1.w};

        float h0 = drv, h1 = 0.f, h2 = 0.f, h3 = 0.f;
        #pragma unroll
        for (int w = 0; w < HW; w += 4) {
            unsigned a = msk[w], bm_ = msk[w+1], c = msk[w+2], d = msk[w+3];
            const float* B0 = g_W11t + (w<<5)*H + j;
            while (a | bm_ | c | d) {
                if (a)   { int i=__ffs(a)-1;   a   &= a-1;   h0 += B0[i*H]; }
                if (bm_) { int i=__ffs(bm_)-1; bm_ &= bm_-1; h1 += B0[(32+i)*H]; }
                if (c)   { int i=__ffs(c)-1;   c   &= c-1;   h2 += B0[(64+i)*H]; }
                if (d)   { int i=__ffs(d)-1;   d   &= d-1;   h3 += B0[(96+i)*H]; }
            }
        }
        float h = (h0 + h1) + (h2 + h3);

        bb = ro*bb + (1.f - ro)*sp;
        float Bt = 0.01f + 1.8f*bb;
        mem = mem*alpha + (1.f - alpha)*h - Bt*sp;
        sp  = (mem - Bt > 0.f) ? 1.f : 0.f;

        unsigned bal = __ballot_sync(0xFFFFFFFFu, sp != 0.f);
        int nxt = cur ^ 1;
        if ((j & 31) == 0) {
            mask[nxt][j >> 5] = bal;
            g_sp1[((size_t)b*T + t)*HW + (j >> 5)] = bal;
        }
        __syncthreads();
        cur = nxt;
        drv = drv_next;
    }
}

// ---------------- layer-2 recurrence FUSED with Wo bit-GEMM + output ---------
// 288 threads: warps 0-7 = 256 neurons; warp 8 = output warp (one step behind).
__global__ __launch_bounds__(288)
void recurrent2_fused(const float* __restrict__ mem0,
                      const float* __restrict__ tau_adp, const float* __restrict__ tau_m,
                      const float* __restrict__ memo0, const float* __restrict__ tau_m_o,
                      const float* __restrict__ bo, float* __restrict__ outp)
{
    int b   = blockIdx.x;
    int tid = threadIdx.x;
    int wid = tid >> 5;
    int lane = tid & 31;
    __shared__ __align__(16) unsigned mask[2][HW];

    // neuron state (warps 0-7)
    float alpha = 0.f, ro = 0.f, mem = 0.f, bb = 0.01f, sp = 0.f;
    const float* dr = g_S12 + (size_t)b*T*H + tid;
    float drv = 0.f;
    // output state (warp 8)
    float alpha_o = 0.f, memo = 0.f, acc = 0.f, bol = 0.f;
    bool act = false;

    if (tid < H) {
        alpha = (float)exp(-1.0 / (double)tau_m[tid]);
        ro    = (float)exp(-1.0 / (double)tau_adp[tid]);
        mem   = mem0[b*H + tid];
        drv   = dr[0];
    } else {
        act = lane < DOUT;
        int l = act ? lane : 0;
        alpha_o = (float)exp(-1.0 / (double)tau_m_o[l]);
        memo    = memo0[b*DOUT + l];
        bol     = bo[l];
    }

    if (tid < 2*HW) ((unsigned*)mask)[tid] = 0u;
    __syncthreads();

    int cur = 0;
    for (int t = 0; t < T; ++t) {
        if (tid < H) {
            float drv_next = (t+1 < T) ? dr[(size_t)(t+1)*H] : 0.f;
            uint4 mq0 = *(const uint4*)&mask[cur][0];
            uint4 mq1 = *(const uint4*)&mask[cur][4];
            unsigned msk[HW] = {mq0.x,mq0.y,mq0.z,mq0.w,mq1.x,mq1.y,mq1.z,mq1.w};

            float h0 = drv, h1 = 0.f, h2 = 0.f, h3 = 0.f;
            #pragma unroll
            for (int w = 0; w < HW; w += 4) {
                unsigned a = msk[w], bm_ = msk[w+1], c = msk[w+2], d = msk[w+3];
                const float* B0 = g_W22t + (w<<5)*H + tid;
                while (a | bm_ | c | d) {
                    if (a)   { int i=__ffs(a)-1;   a   &= a-1;   h0 += B0[i*H]; }
                    if (bm_) { int i=__ffs(bm_)-1; bm_ &= bm_-1; h1 += B0[(32+i)*H]; }
                    if (c)   { int i=__ffs(c)-1;   c   &= c-1;   h2 += B0[(64+i)*H]; }
                    if (d)   { int i=__ffs(d)-1;   d   &= d-1;   h3 += B0[(96+i)*H]; }
                }
            }
            float h = (h0 + h1) + (h2 + h3);

            bb = ro*bb + (1.f - ro)*sp;
            float Bt = 0.01f + 1.8f*bb;
            mem = mem*alpha + (1.f - alpha)*h - Bt*sp;
            sp  = (mem - Bt > 0.f) ? 1.f : 0.f;

            unsigned bal = __ballot_sync(0xFFFFFFFFu, sp != 0.f);
            if (lane == 0) mask[cur ^ 1][wid] = bal;
            drv = drv_next;
        } else if (t > 0) {
            // output warp: process sp2 of step t-1 (in mask[cur])
            uint4 mq0 = *(const uint4*)&mask[cur][0];
            uint4 mq1 = *(const uint4*)&mask[cur][4];
            unsigned msk[HW] = {mq0.x,mq0.y,mq0.z,mq0.w,mq1.x,mq1.y,mq1.z,mq1.w};
            int l = act ? lane : 0;
            float o0 = bol, o1 = 0.f;
            #pragma unroll
            for (int w = 0; w < HW; w += 2) {
                unsigned a = msk[w], c = msk[w+1];
                const float* B0 = g_Wot + (w<<5)*DOUT + l;
                while (a | c) {
                    if (a) { int i=__ffs(a)-1; a &= a-1; o0 += B0[i*DOUT]; }
                    if (c) { int i=__ffs(c)-1; c &= c-1; o1 += B0[(32+i)*DOUT]; }
                }
            }
            memo = memo*alpha_o + (1.f - alpha_o)*(o0 + o1);
            float v = act ? memo : -CUDART_INF_F;
            #pragma unroll
            for (int off = 16; off; off >>= 1)
                v = fmaxf(v, __shfl_xor_sync(0xFFFFFFFFu, v, off));
            float e = act ? expf(memo - v) : 0.f;
            float s = e;
            #pragma unroll
            for (int off = 16; off; off >>= 1)
                s += __shfl_xor_sync(0xFFFFFFFFu, s, off);
            if (t - 1 > 10) acc += e / s;
        }
        __syncthreads();
        cur ^= 1;
    }

    // epilogue: output warp processes final step T-1 (in mask[cur])
    if (tid >= H) {
        uint4 mq0 = *(const uint4*)&mask[cur][0];
        uint4 mq1 = *(const uint4*)&mask[cur][4];
        unsigned msk[HW] = {mq0.x,mq0.y,mq0.z,mq0.w,mq1.x,mq1.y,mq1.z,mq1.w};
        int l = act ? lane : 0;
        float o0 = bol, o1 = 0.f;
        #pragma unroll
        for (int w = 0; w < HW; w += 2) {
            unsigned a = msk[w], c = msk[w+1];
            const float* B0 = g_Wot + (w<<5)*DOUT + l;
            while (a | c) {
                if (a) { int i=__ffs(a)-1; a &= a-1; o0 += B0[i*DOUT]; }
                if (c) { int i=__ffs(c)-1; c &= c-1; o1 += B0[(32+i)*DOUT]; }
            }
        }
        memo = memo*alpha_o + (1.f - alpha_o)*(o0 + o1);
        float v = act ? memo : -CUDART_INF_F;
        #pragma unroll
        for (int off = 16; off; off >>= 1)
            v = fmaxf(v, __shfl_xor_sync(0xFFFFFFFFu, v, off));
        float e = act ? expf(memo - v) : 0.f;
        float s = e;
        #pragma unroll
        for (int off = 16; off; off >>= 1)
            s += __shfl_xor_sync(0xFFFFFFFFu, s, off);
        acc += e / s;   // step T-1=249 > 10 always
        if (act) outp[b*DOUT + lane] = acc;
    }
}

// ---------------- bit-GEMM: S12[m][j] = b12+b22 + sum_{i: bit(m,i)} W12t[i][j]
// 4-row unions with 1-deep load pipeline.
__global__ __launch_bounds__(H)
void bitgemm256_kernel(const float* __restrict__ bias1, const float* __restrict__ bias2,
                       int rows)
{
    const int N = H;
    int j = threadIdx.x;
    float bs = bias1[j] + bias2[j];
    int m0 = blockIdx.x * rows;

    for (int r = 0; r < rows; r += 4) {
        const uint4* p = (const uint4*)(g_sp1 + (size_t)(m0 + r)*HW);
        uint4 A0 = p[0], A1 = p[1], B0q = p[2], B1q = p[3];
        uint4 C0 = p[4], C1 = p[5], D0 = p[6], D1 = p[7];
        unsigned wa[HW] = {A0.x,A0.y,A0.z,A0.w,A1.x,A1.y,A1.z,A1.w};
        unsigned wb[HW] = {B0q.x,B0q.y,B0q.z,B0q.w,B1q.x,B1q.y,B1q.z,B1q.w};
        unsigned wc[HW] = {C0.x,C0.y,C0.z,C0.w,C1.x,C1.y,C1.z,C1.w};
        unsigned wd[HW] = {D0.x,D0.y,D0.z,D0.w,D1.x,D1.y,D1.z,D1.w};
        float h0 = bs, h1 = bs, h2 = bs, h3 = bs;
        #pragma unroll
        for (int w = 0; w < HW; ++w) {
            unsigned a = wa[w], bq = wb[w], c = wc[w], d = wd[w];
            unsigned u = a | bq | c | d;
            const float* base = g_W12t + (w<<5)*N + j;
            unsigned bitc = 0; float vc = 0.f;
            if (u) { int i = __ffs(u)-1; bitc = 1u << i; u &= u-1; vc = base[i*N]; }
            while (bitc) {
                unsigned bitn = 0; float vn = 0.f;
                if (u) { int i = __ffs(u)-1; bitn = 1u << i; u &= u-1; vn = base[i*N]; }
                h0 += (a  & bitc) ? vc : 0.f;
                h1 += (bq & bitc) ? vc : 0.f;
                h2 += (c  & bitc) ? vc : 0.f;
                h3 += (d  & bitc) ? vc : 0.f;
                bitc = bitn; vc = vn;
            }
        }
        float* o = g_S12 + (size_t)(m0 + r)*N + j;
        o[0] = h0; o[N] = h1; o[2*N] = h2; o[3*N] = h3;
    }
}

// ---------------- launch ------------------------------------------------------
extern "C" void kernel_launch(void* const* d_in, const int* in_sizes, int n_in,
                              void* d_out, int out_size)
{
    const float* x        = (const float*)d_in[0];
    const float* mem1_0   = (const float*)d_in[1];
    const float* mem2_0   = (const float*)d_in[2];
    const float* memo_0   = (const float*)d_in[3];
    const float* Wi1      = (const float*)d_in[4];
    const float* bi1      = (const float*)d_in[5];
    const float* W11      = (const float*)d_in[6];
    const float* b11      = (const float*)d_in[7];
    const float* W12      = (const float*)d_in[8];
    const float* b12      = (const float*)d_in[9];
    const float* W22      = (const float*)d_in[10];
    const float* b22      = (const float*)d_in[11];
    const float* Wo       = (const float*)d_in[12];
    const float* bo       = (const float*)d_in[13];
    const float* tau_adp1 = (const float*)d_in[14];
    const float* tau_adp2 = (const float*)d_in[15];
    const float* tau_m1   = (const float*)d_in[16];
    const float* tau_m2   = (const float*)d_in[17];
    const float* tau_mo   = (const float*)d_in[18];
    float* outp = (float*)d_out;

    // 0) transpose weights
    transpose_all<<<(H*H + 255)/256, 256>>>(W11, W12, W22, Wo);

    // A) XW1 = x @ Wi1.T + bi1 + b11   (128x128 tiled, warp-tiled, double buffered)
    dim3 gA(MTOT/128, H/128);
    sgemm128<<<gA, 256>>>(x, Wi1, bi1, b11);

    // B) layer-1 recurrence over all t -> sp1 bits
    recurrent1_kernel<<<BATCH, H>>>(mem1_0, tau_adp1, tau_m1);

    // C) S12 = sp1 @ W12.T + b12 + b22  (parallel quad-row bit-GEMM)
    bitgemm256_kernel<<<MTOT/8, H>>>(b12, b22, 8);

    // D) layer-2 recurrence fused with Wo bit-GEMM + memo/softmax accumulation
    recurrent2_fused<<<BATCH, 288>>>(mem2_0, tau_adp2, tau_m2, memo_0, tau_mo, bo, outp);
}

// round 4
// speedup vs baseline: 2.7636x; 1.4595x over previous
#include <cuda_runtime.h>
#include <math.h>
#include <math_constants.h>

#define BATCH 128
#define T     250
#define DIN   700
#define H     256
#define DOUT  20
#define MTOT  (BATCH*T)
#define LSTR  256            // gmem list stride (worst case all 256 spike)

// ---------------- scratch (static device globals; no dynamic alloc) ----------
__device__ float g_XW1[MTOT*H];       // x@Wi1.T + bi1 + b11   (layer1 drive)
__device__ float g_S12[MTOT*H];       // sp1@W12.T + b12 + b22 (layer2 drive)
__device__ int   g_list1[MTOT*LSTR];  // layer1 spike index lists
__device__ int   g_cnt1 [MTOT];      // layer1 spike counts
__device__ float g_W11t[H*H];         // transposed weights [i][j]
__device__ float g_W12t[H*H];
__device__ float g_W22t[H*H];
__device__ float g_Wot [H*DOUT];

// ---------------- transpose weights ------------------------------------------
__global__ void transpose_all(const float* __restrict__ W11, const float* __restrict__ W12,
                              const float* __restrict__ W22, const float* __restrict__ Wo)
{
    int idx = blockIdx.x * blockDim.x + threadIdx.x;
    if (idx < H*H) {
        int r = idx / H, c = idx % H;
        g_W11t[c*H + r] = W11[idx];
        g_W12t[c*H + r] = W12[idx];
        g_W22t[c*H + r] = W22[idx];
    }
    if (idx < DOUT*H) {
        int r = idx / H, c = idx % H;
        g_Wot[c*DOUT + r] = Wo[idx];
    }
}

// ---------------- Phase A: fp32 SGEMM (NT): C = A*B^T + bias1 + bias2 --------
__global__ __launch_bounds__(256)
void sgemm128(const float* __restrict__ A, const float* __restrict__ Bm,
              const float* __restrict__ bias1, const float* __restrict__ bias2)
{
    const int N = H, K = DIN;
    __shared__ __align__(16) float As[2][8][132];
    __shared__ __align__(16) float Bs[2][8][132];
    float* C = g_XW1;

    int tid  = threadIdx.x;
    int bm   = blockIdx.x * 128, bn = blockIdx.y * 128;
    int lrow = tid >> 1;
    int lk4  = (tid & 1) << 2;
    int warp = tid >> 5;
    int lane = tid & 31;
    int wm   = (warp >> 2) * 64;
    int wn   = (warp & 3) * 32;
    int row  = lane >> 2;
    int col  = lane & 3;
    int moff = wm + row * 8;
    int noff = wn + col * 8;

    const float* Aptr = A  + (size_t)(bm + lrow) * K;
    const float* Bptr = Bm + (size_t)(bn + lrow) * K;

    float4 av, bv;
    {
        int k = lk4;
        bool v = (k < K);
        av = v ? *(const float4*)(Aptr + k) : make_float4(0.f,0.f,0.f,0.f);
        bv = v ? *(const float4*)(Bptr + k) : make_float4(0.f,0.f,0.f,0.f);
    }
    As[0][lk4+0][lrow]=av.x; As[0][lk4+1][lrow]=av.y; As[0][lk4+2][lrow]=av.z; As[0][lk4+3][lrow]=av.w;
    Bs[0][lk4+0][lrow]=bv.x; Bs[0][lk4+1][lrow]=bv.y; Bs[0][lk4+2][lrow]=bv.z; Bs[0][lk4+3][lrow]=bv.w;
    __syncthreads();

    float acc[8][8] = {};
    const int NIT = (K + 7) / 8;

    for (int it = 0; it < NIT; ++it) {
        int cur = it & 1, nxt = cur ^ 1;
        bool more = (it + 1 < NIT);
        if (more) {
            int k = (it + 1) * 8 + lk4;
            bool v = (k < K);
            av = v ? *(const float4*)(Aptr + k) : make_float4(0.f,0.f,0.f,0.f);
            bv = v ? *(const float4*)(Bptr + k) : make_float4(0.f,0.f,0.f,0.f);
        }
        #pragma unroll
        for (int k = 0; k < 8; ++k) {
            float4 a0 = *(const float4*)&As[cur][k][moff];
            float4 a1 = *(const float4*)&As[cur][k][moff+4];
            float4 b0 = *(const float4*)&Bs[cur][k][noff];
            float4 b1 = *(const float4*)&Bs[cur][k][noff+4];
            float af[8] = {a0.x,a0.y,a0.z,a0.w,a1.x,a1.y,a1.z,a1.w};
            float bf[8] = {b0.x,b0.y,b0.z,b0.w,b1.x,b1.y,b1.z,b1.w};
            #pragma unroll
            for (int i = 0; i < 8; ++i)
                #pragma unroll
                for (int jj = 0; jj < 8; ++jj)
                    acc[i][jj] += af[i] * bf[jj];
        }
        if (more) {
            As[nxt][lk4+0][lrow]=av.x; As[nxt][lk4+1][lrow]=av.y; As[nxt][lk4+2][lrow]=av.z; As[nxt][lk4+3][lrow]=av.w;
            Bs[nxt][lk4+0][lrow]=bv.x; Bs[nxt][lk4+1][lrow]=bv.y; Bs[nxt][lk4+2][lrow]=bv.z; Bs[nxt][lk4+3][lrow]=bv.w;
            __syncthreads();
        }
    }

    int ncol = bn + noff;
    float badd[8];
    #pragma unroll
    for (int jj = 0; jj < 8; ++jj) badd[jj] = bias1[ncol+jj] + bias2[ncol+jj];
    #pragma unroll
    for (int i = 0; i < 8; ++i) {
        int rowg = bm + moff + i;
        float4 o0 = make_float4(acc[i][0]+badd[0], acc[i][1]+badd[1], acc[i][2]+badd[2], acc[i][3]+badd[3]);
        float4 o1 = make_float4(acc[i][4]+badd[4], acc[i][5]+badd[5], acc[i][6]+badd[6], acc[i][7]+badd[7]);
        *(float4*)&C[(size_t)rowg*N + ncol    ] = o0;
        *(float4*)&C[(size_t)rowg*N + ncol + 4] = o1;
    }
}

// ---------------- layer-1 recurrence: index-list step loop -------------------
// Per step: consume slist[cur] (counted branch-free loop), update LIF state,
// build slist[nxt] via per-warp popc + cross-warp prefix (2 barriers).
__global__ __launch_bounds__(H)
void recurrent1_kernel(const float* __restrict__ mem0,
                       const float* __restrict__ tau_adp, const float* __restrict__ tau_m)
{
    int b = blockIdx.x;
    int j = threadIdx.x;
    int wid = j >> 5, lane = j & 31;
    __shared__ int slist[2][H];
    __shared__ int scnt[2];
    __shared__ int wnp[8];

    float alpha = (float)exp(-1.0 / (double)tau_m[j]);
    float ro    = (float)exp(-1.0 / (double)tau_adp[j]);
    float mem   = mem0[b*H + j];
    float bb    = 0.01f;
    float sp    = 0.f;

    if (j == 0) scnt[0] = 0;
    __syncthreads();

    const float* dr = g_XW1 + (size_t)b*T*H + j;
    float drv = dr[0];
    int cur = 0;
    for (int t = 0; t < T; ++t) {
        float drv_next = (t+1 < T) ? dr[(size_t)(t+1)*H] : 0.f;
        int c = scnt[cur];
        float h0 = drv, h1 = 0.f, h2 = 0.f, h3 = 0.f;
        int k = 0;
        for (; k + 4 <= c; k += 4) {
            int i0 = slist[cur][k], i1 = slist[cur][k+1];
            int i2 = slist[cur][k+2], i3 = slist[cur][k+3];
            h0 += g_W11t[i0*H + j];
            h1 += g_W11t[i1*H + j];
            h2 += g_W11t[i2*H + j];
            h3 += g_W11t[i3*H + j];
        }
        for (; k < c; ++k) h0 += g_W11t[slist[cur][k]*H + j];
        float h = (h0 + h1) + (h2 + h3);

        bb = ro*bb + (1.f - ro)*sp;
        float Bt = 0.01f + 1.8f*bb;
        mem = mem*alpha + (1.f - alpha)*h - Bt*sp;
        sp  = (mem - Bt > 0.f) ? 1.f : 0.f;

        unsigned bal = __ballot_sync(0xFFFFFFFFu, sp != 0.f);
        if (lane == 0) wnp[wid] = __popc(bal);
        __syncthreads();                       // wnp ready; slist[cur] reads done

        int nxt = cur ^ 1;
        int base = 0, total = 0;
        #pragma unroll
        for (int w = 0; w < 8; ++w) {
            int v = wnp[w];
            total += v;
            if (w < wid) base += v;
        }
        size_t rowidx = (size_t)b*T + t;
        if (sp != 0.f) {
            int pos = base + __popc(bal & ((1u << lane) - 1u));
            slist[nxt][pos] = j;
            g_list1[rowidx*LSTR + pos] = j;
        }
        if (j == 0) {
            scnt[nxt] = total;
            g_cnt1[rowidx] = total;
        }
        __syncthreads();                       // slist[nxt] ready
        cur = nxt;
        drv = drv_next;
    }
}

// ---------------- bit-GEMM via index lists: S12 = sp1 @ W12.T + b12 + b22 ----
// One warp stages each row's list into smem (coalesced), then all 256 threads
// run counted branch-free load/add loops over 8 rows.
__global__ __launch_bounds__(H)
void bitgemm256_kernel(const float* __restrict__ bias1, const float* __restrict__ bias2)
{
    __shared__ int slist[8][LSTR];
    __shared__ int scnt[8];
    int j = threadIdx.x;
    int wid = j >> 5, lane = j & 31;
    int r0 = blockIdx.x * 8;

    {
        size_t row = (size_t)(r0 + wid);
        int c = g_cnt1[row];
        for (int k = lane; k < c; k += 32)
            slist[wid][k] = g_list1[row*LSTR + k];
        if (lane == 0) scnt[wid] = c;
    }
    __syncthreads();

    float bs = bias1[j] + bias2[j];
    #pragma unroll 1
    for (int r = 0; r < 8; ++r) {
        int c = scnt[r];
        float h0 = bs, h1 = 0.f, h2 = 0.f, h3 = 0.f;
        int k = 0;
        for (; k + 4 <= c; k += 4) {
            int i0 = slist[r][k], i1 = slist[r][k+1];
            int i2 = slist[r][k+2], i3 = slist[r][k+3];
            h0 += g_W12t[i0*H + j];
            h1 += g_W12t[i1*H + j];
            h2 += g_W12t[i2*H + j];
            h3 += g_W12t[i3*H + j];
        }
        for (; k < c; ++k) h0 += g_W12t[slist[r][k]*H + j];
        g_S12[(size_t)(r0 + r)*H + j] = (h0 + h1) + (h2 + h3);
    }
}

// ---------------- layer-2 recurrence FUSED with Wo bit-GEMM + output ---------
// 288 threads: warps 0-7 = 256 neurons; warp 8 = output warp (one step behind).
__global__ __launch_bounds__(288)
void recurrent2_fused(const float* __restrict__ mem0,
                      const float* __restrict__ tau_adp, const float* __restrict__ tau_m,
                      const float* __restrict__ memo0, const float* __restrict__ tau_m_o,
                      const float* __restrict__ bo, float* __restrict__ outp)
{
    int b   = blockIdx.x;
    int tid = threadIdx.x;
    int wid = tid >> 5, lane = tid & 31;
    __shared__ int slist[2][H];
    __shared__ int scnt[2];
    __shared__ int wnp[8];

    // neuron state
    float alpha = 0.f, ro = 0.f, mem = 0.f, bb = 0.01f, sp = 0.f;
    const float* dr = g_S12 + (size_t)b*T*H + tid;
    float drv = 0.f;
    // output state
    float alpha_o = 0.f, memo = 0.f, acc = 0.f, bol = 0.f;
    bool act = false;

    if (tid < H) {
        alpha = (float)exp(-1.0 / (double)tau_m[tid]);
        ro    = (float)exp(-1.0 / (double)tau_adp[tid]);
        mem   = mem0[b*H + tid];
        drv   = dr[0];
    } else {
        act = lane < DOUT;
        int l = act ? lane : 0;
        alpha_o = (float)exp(-1.0 / (double)tau_m_o[l]);
        memo    = memo0[b*DOUT + l];
        bol     = bo[l];
    }

    if (tid == 0) scnt[0] = 0;
    __syncthreads();

    int cur = 0;
    for (int t = 0; t < T; ++t) {
        unsigned bal = 0u;
        if (tid < H) {
            float drv_next = (t+1 < T) ? dr[(size_t)(t+1)*H] : 0.f;
            int c = scnt[cur];
            float h0 = drv, h1 = 0.f, h2 = 0.f, h3 = 0.f;
            int k = 0;
            for (; k + 4 <= c; k += 4) {
                int i0 = slist[cur][k], i1 = slist[cur][k+1];
                int i2 = slist[cur][k+2], i3 = slist[cur][k+3];
                h0 += g_W22t[i0*H + tid];
                h1 += g_W22t[i1*H + tid];
                h2 += g_W22t[i2*H + tid];
                h3 += g_W22t[i3*H + tid];
            }
            for (; k < c; ++k) h0 += g_W22t[slist[cur][k]*H + tid];
            float h = (h0 + h1) + (h2 + h3);

            bb = ro*bb + (1.f - ro)*sp;
            float Bt = 0.01f + 1.8f*bb;
            mem = mem*alpha + (1.f - alpha)*h - Bt*sp;
            sp  = (mem - Bt > 0.f) ? 1.f : 0.f;

            bal = __ballot_sync(0xFFFFFFFFu, sp != 0.f);
            if (lane == 0) wnp[wid] = __popc(bal);
            drv = drv_next;
        } else if (t > 0) {
            // output warp: consume sp2 of step t-1 (slist[cur])
            int c = scnt[cur];
            int l = act ? lane : 0;
            float o0 = bol, o1 = 0.f;
            int k = 0;
            for (; k + 2 <= c; k += 2) {
                int i0 = slist[cur][k], i1 = slist[cur][k+1];
                o0 += g_Wot[i0*DOUT + l];
                o1 += g_Wot[i1*DOUT + l];
            }
            for (; k < c; ++k) o0 += g_Wot[slist[cur][k]*DOUT + l];
            memo = memo*alpha_o + (1.f - alpha_o)*(o0 + o1);
            float v = act ? memo : -CUDART_INF_F;
            #pragma unroll
            for (int off = 16; off; off >>= 1)
                v = fmaxf(v, __shfl_xor_sync(0xFFFFFFFFu, v, off));
            float e = act ? expf(memo - v) : 0.f;
            float s = e;
            #pragma unroll
            for (int off = 16; off; off >>= 1)
                s += __shfl_xor_sync(0xFFFFFFFFu, s, off);
            if (t - 1 > 10) acc += e / s;
        }
        __syncthreads();                       // wnp ready; slist[cur] reads done

        int nxt = cur ^ 1;
        if (tid < H) {
            int base = 0, total = 0;
            #pragma unroll
            for (int w = 0; w < 8; ++w) {
                int v = wnp[w];
                total += v;
                if (w < wid) base += v;
            }
            if (sp != 0.f) {
                int pos = base + __popc(bal & ((1u << lane) - 1u));
                slist[nxt][pos] = tid;
            }
            if (tid == 0) scnt[nxt] = total;
        }
        __syncthreads();                       // slist[nxt] ready
        cur = nxt;
    }

    // epilogue: output warp processes final step T-1 (slist[cur])
    if (tid >= H) {
        int c = scnt[cur];
        int l = act ? lane : 0;
        float o0 = bol, o1 = 0.f;
        int k = 0;
        for (; k + 2 <= c; k += 2) {
            int i0 = slist[cur][k], i1 = slist[cur][k+1];
            o0 += g_Wot[i0*DOUT + l];
            o1 += g_Wot[i1*DOUT + l];
        }
        for (; k < c; ++k) o0 += g_Wot[slist[cur][k]*DOUT + l];
        memo = memo*alpha_o + (1.f - alpha_o)*(o0 + o1);
        float v = act ? memo : -CUDART_INF_F;
        #pragma unroll
        for (int off = 16; off; off >>= 1)
            v = fmaxf(v, __shfl_xor_sync(0xFFFFFFFFu, v, off));
        float e = act ? expf(memo - v) : 0.f;
        float s = e;
        #pragma unroll
        for (int off = 16; off; off >>= 1)
            s += __shfl_xor_sync(0xFFFFFFFFu, s, off);
        acc += e / s;   // step T-1=249 > 10 always
        if (act) outp[b*DOUT + lane] = acc;
    }
}

// ---------------- launch ------------------------------------------------------
extern "C" void kernel_launch(void* const* d_in, const int* in_sizes, int n_in,
                              void* d_out, int out_size)
{
    const float* x        = (const float*)d_in[0];
    const float* mem1_0   = (const float*)d_in[1];
    const float* mem2_0   = (const float*)d_in[2];
    const float* memo_0   = (const float*)d_in[3];
    const float* Wi1      = (const float*)d_in[4];
    const float* bi1      = (const float*)d_in[5];
    const float* W11      = (const float*)d_in[6];
    const float* b11      = (const float*)d_in[7];
    const float* W12      = (const float*)d_in[8];
    const float* b12      = (const float*)d_in[9];
    const float* W22      = (const float*)d_in[10];
    const float* b22      = (const float*)d_in[11];
    const float* Wo       = (const float*)d_in[12];
    const float* bo       = (const float*)d_in[13];
    const float* tau_adp1 = (const float*)d_in[14];
    const float* tau_adp2 = (const float*)d_in[15];
    const float* tau_m1   = (const float*)d_in[16];
    const float* tau_m2   = (const float*)d_in[17];
    const float* tau_mo   = (const float*)d_in[18];
    float* outp = (float*)d_out;

    // 0) transpose weights
    transpose_all<<<(H*H + 255)/256, 256>>>(W11, W12, W22, Wo);

    // A) XW1 = x @ Wi1.T + bi1 + b11
    dim3 gA(MTOT/128, H/128);
    sgemm128<<<gA, 256>>>(x, Wi1, bi1, b11);

    // B) layer-1 recurrence -> spike index lists
    recurrent1_kernel<<<BATCH, H>>>(mem1_0, tau_adp1, tau_m1);

    // C) S12 = sp1 @ W12.T + b12 + b22  (index-list GEMM)
    bitgemm256_kernel<<<MTOT/8, H>>>(b12, b22);

    // D) layer-2 recurrence fused with Wo list-GEMM + memo/softmax accumulation
    recurrent2_fused<<<BATCH, 288>>>(mem2_0, tau_adp2, tau_m2, memo_0, tau_mo, bo, outp);
}